// round 2
// baseline (speedup 1.0000x reference)
#include <cuda_runtime.h>
#include <math.h>

#define BB   16
#define SS   4096
#define SP   4097
#define DD   1024
#define HH   16
#define HDIM 64

#define NSC 32     // value-pass s-chunks
#define CS4 129    // 32*129 = 4128 >= 4097
#define CS2 128    // key-pass rows per block
#define NC2 33     // 33*128 = 4224 >= 4097

// ---- scratch (no allocations allowed) ----
__device__ float g_q[BB * DD];                 // scaled projected query
__device__ float g_qk[BB * HH * DD];           // folded query: (q_h Wk_h)
__device__ float g_scores[(size_t)BB * HH * SP];
__device__ float g_upart[(size_t)BB * NSC * HH * DD];
__device__ float g_u[BB * HH * DD];            // sum_s attn * comb_value
__device__ float g_ctx[BB * DD];

// K0: q[b,d] = 0.125 * (query[b,:] . w_in[d,:] + b_in[d])
__global__ void k0_qproj(const float* __restrict__ query,
                         const float* __restrict__ w_in,
                         const float* __restrict__ b_in) {
    int t = threadIdx.x;
    int b = t & 15;
    int dl = t >> 4;
    int d = blockIdx.x * 16 + dl;
    const float* q = query + b * DD;
    const float* w = w_in + (size_t)d * DD;
    float acc = b_in[d];
#pragma unroll 8
    for (int j = 0; j < DD; j++) acc += q[j] * w[j];
    g_q[b * DD + d] = acc * 0.125f;  // hd^-0.5 = 1/8
}

// K1: qk[b,h,j] = sum_i q[b, h*64+i] * w_in[DD + h*64+i, j]
__global__ void k1_qkfold(const float* __restrict__ w_in) {
    __shared__ float qsm[BB * HDIM];
    int h = blockIdx.x;
    int jc = blockIdx.y;
    int t = threadIdx.x;
    for (int idx = t; idx < BB * HDIM; idx += 256) {
        int b = idx >> 6, i = idx & 63;
        qsm[idx] = g_q[b * DD + h * HDIM + i];
    }
    __syncthreads();
    int j = jc * 256 + t;
    float acc[BB];
#pragma unroll
    for (int b = 0; b < BB; b++) acc[b] = 0.f;
    const float* w = w_in + (size_t)(DD + h * HDIM) * DD + j;
#pragma unroll 4
    for (int i = 0; i < HDIM; i++) {
        float wv = w[(size_t)i * DD];
#pragma unroll
        for (int b = 0; b < BB; b++) acc[b] += qsm[b * HDIM + i] * wv;
    }
#pragma unroll
    for (int b = 0; b < BB; b++) g_qk[(b * HH + h) * DD + j] = acc[b];
}

// K2: fused — copy past_key/key into comb_key AND compute scores[b,h,s] = qk[b,h,:].c_s
__global__ void __launch_bounds__(256, 2)
k2_keyscores(const float* __restrict__ past_key,
             const float* __restrict__ key,
             float* __restrict__ comb_key) {
    extern __shared__ float qk_sm[];  // HH*DD floats = 64 KB
    int b = blockIdx.y;
    int t = threadIdx.x;
    {
        const float4* src = (const float4*)(g_qk + (size_t)b * HH * DD);
        float4* dst = (float4*)qk_sm;
        for (int i = t; i < HH * DD / 4; i += 256) dst[i] = src[i];
    }
    __syncthreads();

    int warp = t >> 5, lane = t & 31;
    int s_warp = blockIdx.x * CS2 + warp * 16;

    for (int qd = 0; qd < 4; qd++) {
        int s0 = s_warp + qd * 4;
        float acc[64];
#pragma unroll
        for (int i = 0; i < 64; i++) acc[i] = 0.f;

        const float* srcrow[4];
        float* dstrow[4];
        bool valid[4];
#pragma unroll
        for (int r = 0; r < 4; r++) {
            int s = s0 + r;
            valid[r] = (s < SP);
            srcrow[r] = (s < SS) ? past_key + ((size_t)b * SS + s) * DD
                                 : key + (size_t)b * DD;
            dstrow[r] = comb_key + ((size_t)b * SP + (valid[r] ? s : 0)) * DD;
        }

#pragma unroll
        for (int k = 0; k < 8; k++) {
            int jb = k * 128 + lane * 4;
            float4 c[4];
#pragma unroll
            for (int r = 0; r < 4; r++) {
                if (valid[r]) {
                    c[r] = *(const float4*)(srcrow[r] + jb);
                    *(float4*)(dstrow[r] + jb) = c[r];
                } else {
                    c[r] = make_float4(0.f, 0.f, 0.f, 0.f);
                }
            }
#pragma unroll
            for (int h = 0; h < HH; h++) {
                float4 qv = *(const float4*)(qk_sm + h * DD + jb);
#pragma unroll
                for (int r = 0; r < 4; r++) {
                    acc[h * 4 + r] += qv.x * c[r].x + qv.y * c[r].y +
                                      qv.z * c[r].z + qv.w * c[r].w;
                }
            }
        }
        // butterfly reduce each of 64 partials across the warp
#pragma unroll
        for (int i = 0; i < 64; i++) {
            float v = acc[i];
            v += __shfl_xor_sync(0xffffffffu, v, 16);
            v += __shfl_xor_sync(0xffffffffu, v, 8);
            v += __shfl_xor_sync(0xffffffffu, v, 4);
            v += __shfl_xor_sync(0xffffffffu, v, 2);
            v += __shfl_xor_sync(0xffffffffu, v, 1);
            acc[i] = v;
        }
        if (lane == 0) {
#pragma unroll
            for (int h = 0; h < HH; h++) {
#pragma unroll
                for (int r = 0; r < 4; r++) {
                    int s = s0 + r;
                    if (s < SP)
                        g_scores[((size_t)b * HH + h) * SP + s] = acc[h * 4 + r];
                }
            }
        }
    }
}

// K3: softmax over each (b,h) row of length SP (in place)
__global__ void k3_softmax() {
    __shared__ float red[8];
    int row = blockIdx.x;
    float* sc = g_scores + (size_t)row * SP;
    int t = threadIdx.x;

    float m = -1e30f;
    for (int i = t; i < SP; i += 256) m = fmaxf(m, sc[i]);
#pragma unroll
    for (int o = 16; o; o >>= 1) m = fmaxf(m, __shfl_xor_sync(0xffffffffu, m, o));
    if ((t & 31) == 0) red[t >> 5] = m;
    __syncthreads();
    if (t < 32) {
        float v = (t < 8) ? red[t] : -1e30f;
#pragma unroll
        for (int o = 4; o; o >>= 1) v = fmaxf(v, __shfl_xor_sync(0xffffffffu, v, o));
        if (t == 0) red[0] = v;
    }
    __syncthreads();
    m = red[0];
    __syncthreads();

    float ssum = 0.f;
    for (int i = t; i < SP; i += 256) {
        float e = expf(sc[i] - m);
        sc[i] = e;
        ssum += e;
    }
#pragma unroll
    for (int o = 16; o; o >>= 1) ssum += __shfl_xor_sync(0xffffffffu, ssum, o);
    if ((t & 31) == 0) red[t >> 5] = ssum;
    __syncthreads();
    if (t < 32) {
        float v = (t < 8) ? red[t] : 0.f;
#pragma unroll
        for (int o = 4; o; o >>= 1) v += __shfl_xor_sync(0xffffffffu, v, o);
        if (t == 0) red[0] = v;
    }
    __syncthreads();
    float inv = 1.f / red[0];
    for (int i = t; i < SP; i += 256) sc[i] *= inv;
}

// K4: fused — copy past_value/value into comb_value AND accumulate
//     u_partial[b,sc,h,:] = sum_{s in chunk} attn[b,h,s] * c_s
__global__ void __launch_bounds__(256)
k4_valu(const float* __restrict__ past_value,
        const float* __restrict__ value,
        float* __restrict__ comb_value) {
    __shared__ float attn_sm[HH * CS4];
    int sc = blockIdx.x, b = blockIdx.y;
    int t = threadIdx.x;
    int s0 = sc * CS4;
    int rows = SP - s0;
    if (rows > CS4) rows = CS4;

    for (int h = 0; h < HH; h++) {
        const float* src = g_scores + ((size_t)b * HH + h) * SP + s0;
        for (int si = t; si < rows; si += 256) attn_sm[h * CS4 + si] = src[si];
    }
    __syncthreads();

    int j = t * 4;
    float4 acc[HH];
#pragma unroll
    for (int h = 0; h < HH; h++) acc[h] = make_float4(0.f, 0.f, 0.f, 0.f);

    for (int si = 0; si < rows; si++) {
        int s = s0 + si;
        const float* srcp = (s < SS) ? past_value + ((size_t)b * SS + s) * DD + j
                                     : value + (size_t)b * DD + j;
        float4 c = *(const float4*)srcp;
        *(float4*)(comb_value + ((size_t)b * SP + s) * DD + j) = c;
#pragma unroll
        for (int h = 0; h < HH; h++) {
            float a = attn_sm[h * CS4 + si];
            acc[h].x += a * c.x;
            acc[h].y += a * c.y;
            acc[h].z += a * c.z;
            acc[h].w += a * c.w;
        }
    }
    float* up = g_upart + ((size_t)b * NSC + sc) * HH * DD + j;
#pragma unroll
    for (int h = 0; h < HH; h++) *(float4*)(up + h * DD) = acc[h];
}

// K4b: u = sum over chunks of u_partial
__global__ void k4b_ured() {
    int idx = blockIdx.x * 256 + threadIdx.x;  // 65536 threads, 4 floats each
    int e = idx * 4;
    int b = e >> 14;
    int rest = e & 16383;
    const float* up = g_upart + (size_t)b * NSC * HH * DD + rest;
    float4 s = make_float4(0.f, 0.f, 0.f, 0.f);
#pragma unroll 8
    for (int sc = 0; sc < NSC; sc++) {
        float4 v = *(const float4*)(up + (size_t)sc * HH * DD);
        s.x += v.x; s.y += v.y; s.z += v.z; s.w += v.w;
    }
    *(float4*)(g_u + e) = s;
}

// K5: ctx[b,d] = u[b, d>>6, :] . w_in[2D+d, :] + b_in[2D+d]
__global__ void k5_ctx(const float* __restrict__ w_in,
                       const float* __restrict__ b_in) {
    int t = threadIdx.x;
    int b = t & 15, dl = t >> 4;
    int d = blockIdx.x * 16 + dl;
    int h = d >> 6;
    const float* u = g_u + (b * HH + h) * DD;
    const float* w = w_in + (size_t)(2 * DD + d) * DD;
    float acc = b_in[2 * DD + d];
#pragma unroll 8
    for (int j = 0; j < DD; j++) acc += u[j] * w[j];
    g_ctx[b * DD + d] = acc;
}

// K6: out[b,d] = ctx[b,:] . w_out[d,:] + b_out[d]
__global__ void k6_out(const float* __restrict__ w_out,
                       const float* __restrict__ b_out,
                       float* __restrict__ out) {
    int t = threadIdx.x;
    int b = t & 15, dl = t >> 4;
    int d = blockIdx.x * 16 + dl;
    const float* c = g_ctx + b * DD;
    const float* w = w_out + (size_t)d * DD;
    float acc = b_out[d];
#pragma unroll 8
    for (int j = 0; j < DD; j++) acc += c[j] * w[j];
    out[b * DD + d] = acc;
}

extern "C" void kernel_launch(void* const* d_in, const int* in_sizes, int n_in,
                              void* d_out, int out_size) {
    const float* query      = (const float*)d_in[0];
    const float* key        = (const float*)d_in[1];
    const float* value      = (const float*)d_in[2];
    const float* past_key   = (const float*)d_in[3];
    const float* past_value = (const float*)d_in[4];
    const float* w_in       = (const float*)d_in[5];
    const float* b_in       = (const float*)d_in[6];
    const float* w_out      = (const float*)d_in[7];
    const float* b_out      = (const float*)d_in[8];

    float* out        = (float*)d_out;
    float* comb_key   = out + BB * DD;
    float* comb_value = comb_key + (size_t)BB * SP * DD;

    // 64 KB dynamic smem for the folded-query tile (idempotent; not a stream op)
    cudaFuncSetAttribute(k2_keyscores, cudaFuncAttributeMaxDynamicSharedMemorySize,
                         HH * DD * (int)sizeof(float));

    k0_qproj<<<64, 256>>>(query, w_in, b_in);
    k1_qkfold<<<dim3(16, 4), 256>>>(w_in);
    k2_keyscores<<<dim3(NC2, BB), 256, HH * DD * sizeof(float)>>>(past_key, key, comb_key);
    k3_softmax<<<BB * HH, 256>>>();
    k4_valu<<<dim3(NSC, BB), 256>>>(past_value, value, comb_value);
    k4b_ured<<<256, 256>>>();
    k5_ctx<<<64, 256>>>(w_in, b_in);
    k6_out<<<64, 256>>>(w_out, b_out, out);
}